// round 17
// baseline (speedup 1.0000x reference)
#include <cuda_runtime.h>
#include <cuda_bf16.h>
#include <math.h>
#include <stdint.h>

// Problem constants: B=4, L=1024, E=8, D=512, NLAYERS=2
#define Dc 512
#define Gc 4096   // B*L
#define Ec 8
#define MAXEDGE 256
#define KZ 4      // split-K factor for fold GEMMs
#define KLEN 128  // Dc / KZ
#define FOLD_BLOCKS 256

// ---------------- scratch (device globals; no allocations allowed) ----------
__device__ __align__(16) float g_partW[KZ * Dc * Dc];   // fold1 partials
__device__ __align__(16) float g_partb[KZ * Dc];
__device__ __align__(16) float g_partW2[KZ * Dc * Dc];  // fold2 partials
__device__ __align__(16) float g_partb2[KZ * Dc];
__device__ __align__(16) float g_bf[Dc];
__device__ __align__(16) __nv_bfloat16 g_z0h[Gc*Dc];   // hi(z0)       [m][k]
__device__ __align__(16) __nv_bfloat16 g_z0l[Gc*Dc];   // lo residual  [m][k]
__device__ __align__(16) __nv_bfloat16 g_Wfh[Dc*Dc];   // hi(Wf^T)     [n][k]
__device__ __align__(16) __nv_bfloat16 g_Wfl[Dc*Dc];   // lo(Wf^T)     [n][k]
__device__ __align__(16) float g_y[Gc*Dc];

// ---------------- f32x2 packed helpers (FFMA2, for fold GEMMs) --------------
__device__ __forceinline__ unsigned long long bcast2(float x) {
    unsigned long long r;
    asm("mov.b64 %0, {%1, %1};" : "=l"(r) : "f"(x));
    return r;
}
__device__ __forceinline__ void fma2(unsigned long long& d,
                                     unsigned long long a, unsigned long long b) {
    asm("fma.rn.f32x2 %0, %1, %2, %0;" : "+l"(d) : "l"(a), "l"(b));
}
__device__ __forceinline__ float2 unpack2(unsigned long long p) {
    float2 v;
    asm("mov.b64 {%0, %1}, %2;" : "=f"(v.x), "=f"(v.y) : "l"(p));
    return v;
}
__device__ __forceinline__ unsigned short bfu(__nv_bfloat16 h) {
    return *reinterpret_cast<unsigned short*>(&h);
}

// ---------------- 1) fold1: split-K  partW = W1 @ W2 (+bias GEMV partials) --
__global__ void __launch_bounds__(256)
k_fold1(const float* __restrict__ A, const float* __restrict__ B,
        const float* __restrict__ vsrc,
        float* __restrict__ partW, float* __restrict__ partb) {
    constexpr int BM = 64, BN = 64, BK = 16, TM = 4, TN = 4;
    __shared__ __align__(16) float As[2][BK][BM + 4];
    __shared__ __align__(16) float Bs[2][BK][BN + 4];
    __shared__ float vsm[KLEN];

    const int t = threadIdx.x;
    const int fid = blockIdx.x;
    const int bx = fid & 7, by = (fid >> 3) & 7, kz = fid >> 6;
    const int brow = by * BM;
    const int bcol = bx * BN;
    const int kbase = kz * KLEN;
    const int tcol = (t % (BN / TN)) * TN;
    const int trow = (t / (BN / TN)) * TM;
    const int ar = t / (BK / 4);
    const int ac = (t % (BK / 4)) * 4;
    const int br = t / (BN / 4);
    const int bc = (t % (BN / 4)) * 4;

    for (int i = t; i < KLEN; i += 256) vsm[i] = vsrc[kbase + i];
    const bool bth = (by == 0) && (t < BN);
    float bacc = 0.f;

    unsigned long long accp[TM / 2][TN];
#pragma unroll
    for (int m = 0; m < TM / 2; m++)
#pragma unroll
        for (int n = 0; n < TN; n++) accp[m][n] = 0ull;

    float4 afrag, bfrag;
    auto ldg = [&](int k0) {
        afrag = *reinterpret_cast<const float4*>(
            &A[(size_t)(brow + ar) * Dc + kbase + k0 + ac]);
        bfrag = *reinterpret_cast<const float4*>(
            &B[(size_t)(kbase + k0 + br) * Dc + bcol + bc]);
    };
    auto sts = [&](int buf) {
        As[buf][ac + 0][ar] = afrag.x;
        As[buf][ac + 1][ar] = afrag.y;
        As[buf][ac + 2][ar] = afrag.z;
        As[buf][ac + 3][ar] = afrag.w;
        *reinterpret_cast<float4*>(&Bs[buf][br][bc]) = bfrag;
    };

    ldg(0);
    sts(0);
    __syncthreads();

    int buf = 0;
    for (int k0 = 0; k0 < KLEN; k0 += BK) {
        const bool has_next = (k0 + BK) < KLEN;
        if (has_next) ldg(k0 + BK);
#pragma unroll
        for (int kk = 0; kk < BK; kk++) {
            unsigned long long rap[TM / 2];
            const unsigned long long* ap =
                reinterpret_cast<const unsigned long long*>(&As[buf][kk][trow]);
#pragma unroll
            for (int m = 0; m < TM / 2; m++) rap[m] = ap[m];
            float rb[TN];
#pragma unroll
            for (int n = 0; n < TN; n += 4)
                *reinterpret_cast<float4*>(&rb[n]) =
                    *reinterpret_cast<const float4*>(&Bs[buf][kk][tcol + n]);
            unsigned long long rbb[TN];
#pragma unroll
            for (int n = 0; n < TN; n++) rbb[n] = bcast2(rb[n]);
#pragma unroll
            for (int m = 0; m < TM / 2; m++)
#pragma unroll
                for (int n = 0; n < TN; n++) fma2(accp[m][n], rap[m], rbb[n]);
        }
        if (bth) {
#pragma unroll 4
            for (int kk = 0; kk < BK; kk++)
                bacc = fmaf(vsm[k0 + kk], Bs[buf][kk][t], bacc);
        }
        if (has_next) {
            sts(buf ^ 1);
            __syncthreads();
            buf ^= 1;
        }
    }

    if (bth) partb[kz * Dc + bcol + t] = bacc;
    float* W = partW + (size_t)kz * Dc * Dc;
#pragma unroll
    for (int m = 0; m < TM / 2; m++)
#pragma unroll
        for (int n = 0; n < TN; n++) {
            float2 v = unpack2(accp[m][n]);
            W[(size_t)(brow + trow + 2 * m + 0) * Dc + bcol + tcol + n] = v.x;
            W[(size_t)(brow + trow + 2 * m + 1) * Dc + bcol + tcol + n] = v.y;
        }
}

// ---------------- 2) fused reduce + fold2' ----------------------------------
// blocks [0, FOLD_BLOCKS): fold2' = (sum of fold1 partials) @ comb_w, with the
//   b1f bias GEMV (inline mix for s2) — compute-bound.
// blocks [FOLD_BLOCKS, 2304): weighted expert reduce -> z0 split bf16
//   (inline mix for w1) — HBM-bound. Independent roles overlap in one launch.
__global__ void __launch_bounds__(256)
k_redfold2(const float* __restrict__ X, const int* __restrict__ he, int nnz,
           const float* __restrict__ Bmat, const float* __restrict__ lin_b,
           const float* __restrict__ pW1, const float* __restrict__ pb1,
           float* __restrict__ partW, float* __restrict__ partb) {
    __shared__ float M2s[Ec][Ec];
    __shared__ float degn[Ec];
    __shared__ float dege[MAXEDGE];
    __shared__ float Dinv[Ec];
    __shared__ float Binv[MAXEDGE];
    __shared__ float mixout[Ec + 1];   // w1s[0..7] or s2 at [8]
    __shared__ __align__(16) float As[2][16][68];
    __shared__ __align__(16) float Bs[2][16][68];
    __shared__ float vsm[KLEN];

    const int t = threadIdx.x;
    const bool fold_role = (blockIdx.x < FOLD_BLOCKS);
    const int fid = blockIdx.x;
    const int bx = fid & 7, by = (fid >> 3) & 7, kz = fid >> 6;
    const int kbase = kz * KLEN;

    // inline mix (needed by reduce blocks for w1; by fold by==0 blocks for s2)
    const bool need_mix = !fold_role || (by == 0);
    if (need_mix) {
        const int* node = he;
        const int* edge = he + nnz;
        if (t < Ec) degn[t] = 0.f;
        for (int e = t; e < MAXEDGE; e += 256) dege[e] = 0.f;
        if (t < Ec * Ec) ((float*)M2s)[t] = 0.f;
        __syncthreads();
        for (int i = t; i < nnz; i += 256) {
            atomicAdd(&degn[node[i]], 1.f);
            atomicAdd(&dege[edge[i]], 1.f);
        }
        __syncthreads();
        if (t < Ec) Dinv[t] = degn[t] > 0.f ? 1.f / degn[t] : 0.f;
        for (int e = t; e < MAXEDGE; e += 256)
            Binv[e] = dege[e] > 0.f ? 1.f / dege[e] : 0.f;
        __syncthreads();
        int total = nnz * nnz;
        for (int p = t; p < total; p += 256) {
            int i = p % nnz, j = p / nnz;
            int ei = edge[i];
            if (ei == edge[j])
                atomicAdd(&M2s[node[j]][node[i]], Dinv[node[j]] * Binv[ei]);
        }
        __syncthreads();
        if (t == 0) {
            float w2[Ec], s2 = 0.f;
            for (int u = 0; u < Ec; u++) {
                float s = 0.f;
                for (int v = 0; v < Ec; v++) s += M2s[v][u];
                w2[u] = s / (float)Ec;
                s2 += w2[u];
            }
            for (int q = 0; q < Ec; q++) {
                float s = 0.f;
                for (int u = 0; u < Ec; u++) s += M2s[u][q] * w2[u];
                mixout[q] = s;
            }
            mixout[Ec] = s2;
        }
        __syncthreads();
    }

    if (fold_role) {
        constexpr int BM = 64, BN = 64, BK = 16, TM = 4, TN = 4;
        const int brow = by * BM;
        const int bcol = bx * BN;
        const int tcol = (t % (BN / TN)) * TN;
        const int trow = (t / (BN / TN)) * TM;
        const int ar = t / (BK / 4);
        const int ac = (t % (BK / 4)) * 4;
        const int br = t / (BN / 4);
        const int bc = (t % (BN / 4)) * 4;

        if (by == 0) {
            float s2 = mixout[Ec];
            for (int i = t; i < KLEN; i += 256) {
                float s = ((pb1[kbase + i] + pb1[Dc + kbase + i])
                           + pb1[2 * Dc + kbase + i]) + pb1[3 * Dc + kbase + i];
                vsm[i] = s2 * s + lin_b[Dc + kbase + i];   // b1f chunk
            }
            __syncthreads();
        }
        const bool bth = (by == 0) && (t < BN);
        float bacc = 0.f;

        unsigned long long accp[TM / 2][TN];
#pragma unroll
        for (int m = 0; m < TM / 2; m++)
#pragma unroll
            for (int n = 0; n < TN; n++) accp[m][n] = 0ull;

        float4 afrag, bfrag;
        auto ldg = [&](int k0) {
            size_t aidx = (size_t)(brow + ar) * Dc + kbase + k0 + ac;
            float4 p0 = *reinterpret_cast<const float4*>(pW1 + aidx);
            float4 p1 = *reinterpret_cast<const float4*>(pW1 + (size_t)Dc * Dc + aidx);
            float4 p2 = *reinterpret_cast<const float4*>(pW1 + 2 * (size_t)Dc * Dc + aidx);
            float4 p3 = *reinterpret_cast<const float4*>(pW1 + 3 * (size_t)Dc * Dc + aidx);
            afrag.x = ((p0.x + p1.x) + p2.x) + p3.x;
            afrag.y = ((p0.y + p1.y) + p2.y) + p3.y;
            afrag.z = ((p0.z + p1.z) + p2.z) + p3.z;
            afrag.w = ((p0.w + p1.w) + p2.w) + p3.w;
            bfrag = *reinterpret_cast<const float4*>(
                &Bmat[(size_t)(kbase + k0 + br) * Dc + bcol + bc]);
        };
        auto sts = [&](int buf) {
            As[buf][ac + 0][ar] = afrag.x;
            As[buf][ac + 1][ar] = afrag.y;
            As[buf][ac + 2][ar] = afrag.z;
            As[buf][ac + 3][ar] = afrag.w;
            *reinterpret_cast<float4*>(&Bs[buf][br][bc]) = bfrag;
        };

        ldg(0);
        sts(0);
        __syncthreads();

        int buf = 0;
        for (int k0 = 0; k0 < KLEN; k0 += 16) {
            const bool has_next = (k0 + 16) < KLEN;
            if (has_next) ldg(k0 + 16);
#pragma unroll
            for (int kk = 0; kk < 16; kk++) {
                unsigned long long rap[TM / 2];
                const unsigned long long* ap =
                    reinterpret_cast<const unsigned long long*>(&As[buf][kk][trow]);
#pragma unroll
                for (int m = 0; m < TM / 2; m++) rap[m] = ap[m];
                float rb[TN];
#pragma unroll
                for (int n = 0; n < TN; n += 4)
                    *reinterpret_cast<float4*>(&rb[n]) =
                        *reinterpret_cast<const float4*>(&Bs[buf][kk][tcol + n]);
                unsigned long long rbb[TN];
#pragma unroll
                for (int n = 0; n < TN; n++) rbb[n] = bcast2(rb[n]);
#pragma unroll
                for (int m = 0; m < TM / 2; m++)
#pragma unroll
                    for (int n = 0; n < TN; n++) fma2(accp[m][n], rap[m], rbb[n]);
            }
            if (bth) {
#pragma unroll 4
                for (int kk = 0; kk < 16; kk++)
                    bacc = fmaf(vsm[k0 + kk], Bs[buf][kk][t], bacc);
            }
            if (has_next) {
                sts(buf ^ 1);
                __syncthreads();
                buf ^= 1;
            }
        }

        if (bth) partb[kz * Dc + bcol + t] = bacc;
        float* W = partW + (size_t)kz * Dc * Dc;
#pragma unroll
        for (int m = 0; m < TM / 2; m++)
#pragma unroll
            for (int n = 0; n < TN; n++) {
                float2 v = unpack2(accp[m][n]);
                W[(size_t)(brow + trow + 2 * m + 0) * Dc + bcol + tcol + n] = v.x;
                W[(size_t)(brow + trow + 2 * m + 1) * Dc + bcol + tcol + n] = v.y;
            }
    } else {
        int i = (blockIdx.x - FOLD_BLOCKS) * 256 + t;
        int g  = i >> 7;
        int d4 = i & 127;
        const float4* xp =
            reinterpret_cast<const float4*>(X) + (size_t)g * Ec * (Dc / 4) + d4;
        float w[Ec];
#pragma unroll
        for (int u = 0; u < Ec; u++) w[u] = mixout[u];
        float4 acc = make_float4(0.f, 0.f, 0.f, 0.f);
#pragma unroll
        for (int u = 0; u < Ec; u++) {
            float4 v = xp[(size_t)u * (Dc / 4)];
            acc.x = fmaf(w[u], v.x, acc.x);
            acc.y = fmaf(w[u], v.y, acc.y);
            acc.z = fmaf(w[u], v.z, acc.z);
            acc.w = fmaf(w[u], v.w, acc.w);
        }
        float a[4] = {acc.x, acc.y, acc.z, acc.w};
        unsigned short h[4], l[4];
#pragma unroll
        for (int j = 0; j < 4; j++) {
            __nv_bfloat16 hb = __float2bfloat16(a[j]);
            __nv_bfloat16 lb = __float2bfloat16(a[j] - __bfloat162float(hb));
            h[j] = bfu(hb);
            l[j] = bfu(lb);
        }
        uint2 uh, ul;
        uh.x = (uint32_t)h[0] | ((uint32_t)h[1] << 16);
        uh.y = (uint32_t)h[2] | ((uint32_t)h[3] << 16);
        ul.x = (uint32_t)l[0] | ((uint32_t)l[1] << 16);
        ul.y = (uint32_t)l[2] | ((uint32_t)l[3] << 16);
        *reinterpret_cast<uint2*>(g_z0h + (size_t)i * 4) = uh;
        *reinterpret_cast<uint2*>(g_z0l + (size_t)i * 4) = ul;
    }
}

// ---------------- 3) combine -> Wf^T split-bf16 + bf ------------------------
__global__ void k_comb2(const float* __restrict__ extra_b) {
    int i = blockIdx.x * blockDim.x + threadIdx.x;
    const float4* p = reinterpret_cast<const float4*>(g_partW2);
    constexpr int STRIDE = Dc * Dc / 4;
    float4 a = p[i], b = p[i + STRIDE], c = p[i + 2 * STRIDE], d = p[i + 3 * STRIDE];
    float r[4];
    r[0] = ((a.x + b.x) + c.x) + d.x;
    r[1] = ((a.y + b.y) + c.y) + d.y;
    r[2] = ((a.z + b.z) + c.z) + d.z;
    r[3] = ((a.w + b.w) + c.w) + d.w;
    int k = i >> 7;
    int n = (i & 127) * 4;
#pragma unroll
    for (int j = 0; j < 4; j++) {
        __nv_bfloat16 hb = __float2bfloat16(r[j]);
        __nv_bfloat16 lb = __float2bfloat16(r[j] - __bfloat162float(hb));
        g_Wfh[(size_t)(n + j) * Dc + k] = hb;
        g_Wfl[(size_t)(n + j) * Dc + k] = lb;
    }
    if (i < Dc) {
        float s = ((g_partb2[i] + g_partb2[Dc + i]) + g_partb2[2 * Dc + i])
                  + g_partb2[3 * Dc + i];
        g_bf[i] = s + extra_b[i];
    }
}

// ---------------- 4) main GEMM: mma.sync bf16-split, 2 CTAs/SM --------------
// BM=64, BN=128 -> 256 CTAs; 256 threads, 8 warps as 2(m) x 4(n), warp 32x32.
// Single fragment set + smem double buffer; latency hidden by 16 warps/SM.
#define MM_BK   16
#define MM_LDK  24                          // 48B rows, ldmatrix conflict-free
#define TA_E    (64 * MM_LDK)               // A tile elems (64 rows)
#define TB_E    (128 * MM_LDK)              // B tile elems (128 rows)
#define BUF_E   (2 * TA_E + 2 * TB_E)       // Ah, Al, Bh, Bl = 9216 elems
#define MM_SMEM (2 * BUF_E * 2)             // 36864 bytes

__device__ __forceinline__ void mma16816(float* c, uint32_t a0, uint32_t a1,
                                         uint32_t a2, uint32_t a3,
                                         uint32_t b0, uint32_t b1) {
    asm volatile(
        "mma.sync.aligned.m16n8k16.row.col.f32.bf16.bf16.f32 "
        "{%0,%1,%2,%3}, {%4,%5,%6,%7}, {%8,%9}, {%0,%1,%2,%3};"
        : "+f"(c[0]), "+f"(c[1]), "+f"(c[2]), "+f"(c[3])
        : "r"(a0), "r"(a1), "r"(a2), "r"(a3), "r"(b0), "r"(b1));
}

__device__ __forceinline__ void ldm_x4(uint32_t& r0, uint32_t& r1,
                                       uint32_t& r2, uint32_t& r3, uint32_t addr) {
    asm volatile(
        "ldmatrix.sync.aligned.m8n8.x4.shared.b16 {%0,%1,%2,%3}, [%4];"
        : "=r"(r0), "=r"(r1), "=r"(r2), "=r"(r3) : "r"(addr));
}

__global__ void __launch_bounds__(256, 2) k_main_mma() {
    extern __shared__ __nv_bfloat16 sm[];
    const int tid  = threadIdx.x;
    const int lane = tid & 31;
    const int wid  = tid >> 5;          // 0..7
    const int wm   = wid >> 2;          // 0..1 -> m offset wm*32
    const int wn   = wid & 3;           // 0..3 -> n offset wn*32
    const int brow = blockIdx.y * 64;
    const int bcol = blockIdx.x * 128;
    const int g    = lane >> 2;
    const int tg   = lane & 3;

    // staging: A tiles (64 rows) use tid<128 for Ah / tid>=128 for Al;
    // B tiles (128 rows): every thread loads one uint4 for Bh and one for Bl.
    const int atile = tid >> 7;
    const int ra = (tid & 127) >> 1, ca = (tid & 1) * 8;
    const int rb = tid >> 1,         cb = (tid & 1) * 8;

    // ldmatrix lane address components
    const int sel = lane >> 3;
    const int rim = lane & 7;
    const int a_row = (sel & 1) * 8 + rim;
    const int a_k   = (sel >> 1) * 8;
    const int b_row = (sel >> 1) * 8 + rim;
    const int b_k   = (sel & 1) * 8;

    float acc[2][4][4];
#pragma unroll
    for (int mf = 0; mf < 2; mf++)
#pragma unroll
        for (int nf = 0; nf < 4; nf++)
#pragma unroll
            for (int q = 0; q < 4; q++) acc[mf][nf][q] = 0.f;

    uint4 pfa, pfb0, pfb1;
    auto ldg = [&](int kb) {
        const __nv_bfloat16* asrc = atile ? g_z0l : g_z0h;
        pfa  = *(const uint4*)(asrc + (size_t)(brow + ra) * Dc + kb + ca);
        pfb0 = *(const uint4*)(g_Wfh + (size_t)(bcol + rb) * Dc + kb + cb);
        pfb1 = *(const uint4*)(g_Wfl + (size_t)(bcol + rb) * Dc + kb + cb);
    };
    auto sts = [&](int buf) {
        __nv_bfloat16* base = sm + buf * BUF_E;
        *(uint4*)(base + atile * TA_E + ra * MM_LDK + ca) = pfa;
        *(uint4*)(base + 2 * TA_E + rb * MM_LDK + cb) = pfb0;
        *(uint4*)(base + 2 * TA_E + TB_E + rb * MM_LDK + cb) = pfb1;
    };

    ldg(0);
    sts(0);
    __syncthreads();

    int buf = 0;
    for (int kt = 0; kt < Dc / MM_BK; kt++) {
        const bool has_next = (kt + 1) < (Dc / MM_BK);
        if (has_next) ldg((kt + 1) * MM_BK);

        const __nv_bfloat16* base = sm + buf * BUF_E;
        uint32_t Ah[2][4], Al[2][4], Bh[4][2], Bl[4][2];
#pragma unroll
        for (int mf = 0; mf < 2; mf++) {
            uint32_t ah = (uint32_t)__cvta_generic_to_shared(
                base + 0 * TA_E + (wm * 32 + mf * 16 + a_row) * MM_LDK + a_k);
            ldm_x4(Ah[mf][0], Ah[mf][1], Ah[mf][2], Ah[mf][3], ah);
            uint32_t al = (uint32_t)__cvta_generic_to_shared(
                base + 1 * TA_E + (wm * 32 + mf * 16 + a_row) * MM_LDK + a_k);
            ldm_x4(Al[mf][0], Al[mf][1], Al[mf][2], Al[mf][3], al);
        }
#pragma unroll
        for (int nf2 = 0; nf2 < 2; nf2++) {
            uint32_t bh = (uint32_t)__cvta_generic_to_shared(
                base + 2 * TA_E + (wn * 32 + nf2 * 16 + b_row) * MM_LDK + b_k);
            ldm_x4(Bh[nf2 * 2][0], Bh[nf2 * 2][1],
                   Bh[nf2 * 2 + 1][0], Bh[nf2 * 2 + 1][1], bh);
            uint32_t bl = (uint32_t)__cvta_generic_to_shared(
                base + 2 * TA_E + TB_E + (wn * 32 + nf2 * 16 + b_row) * MM_LDK + b_k);
            ldm_x4(Bl[nf2 * 2][0], Bl[nf2 * 2][1],
                   Bl[nf2 * 2 + 1][0], Bl[nf2 * 2 + 1][1], bl);
        }
        // term-major: per-accumulator order unchanged -> bit-exact
#pragma unroll
        for (int mf = 0; mf < 2; mf++)
#pragma unroll
            for (int nf = 0; nf < 4; nf++)
                mma16816(acc[mf][nf], Ah[mf][0], Ah[mf][1], Ah[mf][2], Ah[mf][3],
                         Bh[nf][0], Bh[nf][1]);
#pragma unroll
        for (int mf = 0; mf < 2; mf++)
#pragma unroll
            for (int nf = 0; nf < 4; nf++)
                mma16816(acc[mf][nf], Ah[mf][0], Ah[mf][1], Ah[mf][2], Ah[mf][3],
                         Bl[nf][0], Bl[nf][1]);
#pragma unroll
        for (int mf = 0; mf < 2; mf++)
#pragma unroll
            for (int nf = 0; nf < 4; nf++)
                mma16816(acc[mf][nf], Al[mf][0], Al[mf][1], Al[mf][2], Al[mf][3],
                         Bh[nf][0], Bh[nf][1]);

        if (has_next) {
            sts(buf ^ 1);
            __syncthreads();
            buf ^= 1;
        }
    }

    // epilogue: bias + exact GELU
#pragma unroll
    for (int mf = 0; mf < 2; mf++) {
#pragma unroll
        for (int nf = 0; nf < 4; nf++) {
            int mbase = brow + wm * 32 + mf * 16 + g;
            int nbase = bcol + wn * 32 + nf * 8 + tg * 2;
            float b0v = g_bf[nbase], b1v = g_bf[nbase + 1];
            float x0 = acc[mf][nf][0] + b0v;
            float x1 = acc[mf][nf][1] + b1v;
            float x2 = acc[mf][nf][2] + b0v;
            float x3 = acc[mf][nf][3] + b1v;
            float2 lo, hi;
            lo.x = 0.5f * x0 * (1.f + erff(x0 * 0.70710678118654752f));
            lo.y = 0.5f * x1 * (1.f + erff(x1 * 0.70710678118654752f));
            hi.x = 0.5f * x2 * (1.f + erff(x2 * 0.70710678118654752f));
            hi.y = 0.5f * x3 * (1.f + erff(x3 * 0.70710678118654752f));
            *reinterpret_cast<float2*>(g_y + (size_t)mbase * Dc + nbase) = lo;
            *reinterpret_cast<float2*>(g_y + (size_t)(mbase + 8) * Dc + nbase) = hi;
        }
    }
}

// ---------------- 5) LayerNorm over D=512 -----------------------------------
__global__ void k_ln(const float* __restrict__ Y, const float* __restrict__ gam,
                     const float* __restrict__ bet, float* __restrict__ out) {
    int row = blockIdx.x;
    const float* y = Y + (size_t)row * Dc;
    int t = threadIdx.x;
    float v[4];
    float s = 0.f;
#pragma unroll
    for (int i = 0; i < 4; i++) { v[i] = y[t + i * 128]; s += v[i]; }
    __shared__ float red[4];
#pragma unroll
    for (int o = 16; o; o >>= 1) s += __shfl_xor_sync(0xffffffffu, s, o);
    if ((t & 31) == 0) red[t >> 5] = s;
    __syncthreads();
    float mu = (red[0] + red[1] + red[2] + red[3]) * (1.f / Dc);
    __syncthreads();
    float d2 = 0.f;
#pragma unroll
    for (int i = 0; i < 4; i++) { float d = v[i] - mu; d2 += d * d; }
#pragma unroll
    for (int o = 16; o; o >>= 1) d2 += __shfl_xor_sync(0xffffffffu, d2, o);
    if ((t & 31) == 0) red[t >> 5] = d2;
    __syncthreads();
    float var = (red[0] + red[1] + red[2] + red[3]) * (1.f / Dc);
    float rs = rsqrtf(var + 1e-5f);
#pragma unroll
    for (int i = 0; i < 4; i++) {
        int c = t + i * 128;
        out[(size_t)row * Dc + c] = (v[i] - mu) * rs * gam[c] + bet[c];
    }
}

// ---------------- launch -----------------------------------------------------
extern "C" void kernel_launch(void* const* d_in, const int* in_sizes, int n_in,
                              void* d_out, int out_size) {
    const float* x      = (const float*)d_in[0];
    const int*   he     = (const int*)  d_in[1];
    const float* lin_w  = (const float*)d_in[2];
    const float* lin_b  = (const float*)d_in[3];
    const float* comb_w = (const float*)d_in[4];
    const float* comb_b = (const float*)d_in[5];
    const float* ln_g   = (const float*)d_in[6];
    const float* ln_b   = (const float*)d_in[7];
    float* out = (float*)d_out;
    const int nnz = in_sizes[1] / 2;

    float *p_y, *p_partW, *p_partb, *p_partW2, *p_partb2;
    cudaGetSymbolAddress((void**)&p_y,      g_y);
    cudaGetSymbolAddress((void**)&p_partW,  g_partW);
    cudaGetSymbolAddress((void**)&p_partb,  g_partb);
    cudaGetSymbolAddress((void**)&p_partW2, g_partW2);
    cudaGetSymbolAddress((void**)&p_partb2, g_partb2);

    cudaFuncSetAttribute(k_main_mma,
                         cudaFuncAttributeMaxDynamicSharedMemorySize, MM_SMEM);

    // 1) fold1: partW = W1 @ W2 (split-K) + bias partials
    k_fold1<<<FOLD_BLOCKS, 256>>>(lin_w, lin_w + Dc * Dc, lin_b,
                                  p_partW, p_partb);

    // 2) fused: fold2' (blocks 0-255, consumes fold1 partials) +
    //           weighted expert reduce (blocks 256-2303, independent)
    {
        int grid = FOLD_BLOCKS + Gc * (Dc / 4) / 256;   // 2304
        k_redfold2<<<grid, 256>>>(x, he, nnz, comb_w, lin_b,
                                  p_partW, p_partb, p_partW2, p_partb2);
    }

    // 3) combine -> Wf^T split-bf16 + bf
    k_comb2<<<Dc * Dc / 4 / 256, 256>>>(comb_b);

    // 4) main GEMM (mma.sync, ldmatrix, 2 CTAs/SM): y = gelu(z0@Wf + bf)
    {
        dim3 grid(Dc / 128, Gc / 64);   // (4, 64) = 256 CTAs, ~2/SM, 1 wave
        k_main_mma<<<grid, 256, MM_SMEM>>>();
    }

    // 5) LayerNorm -> output
    k_ln<<<Gc, 128>>>(p_y, ln_g, ln_b, out);
}